// round 12
// baseline (speedup 1.0000x reference)
#include <cuda_runtime.h>

// Log-sparse causal attention, B=4, L=2048, H=8, E=D=64, fp32.
// Query l attends keys l-d for d in OFF (17 offsets), d <= l.
// Half-warp (16 lanes) processes QG=4 consecutive queries, sharing K/V row
// loads across the group (45 distinct rows). Score array split lo(8)/s8/hi(8).
// NEW (R12): each CTA loops over 8 consecutive 32-query chunks (256 queries)
// in ascending order, so a K/V row fetched for the causal window is re-used
// from L1 when it later appears as the d=21/37/69/133 far row of later
// queries. This cuts L2->L1 traffic (the measured bottleneck) ~2.5x.

constexpr int Bc = 4, Lc = 2048, Hc = 8;
constexpr float SCALE = 0.125f;      // 1/sqrt(64)
constexpr int ROWSTR = Hc * 64;      // 512 elements per l-step
constexpr int ITERS = 8;             // 8 x 32 = 256 queries per CTA

// 45 distinct relative rows e (row = l0 - e) covering all (j in 0..3, d in OFF)
__device__ constexpr int EREL[45] = {
    -3,-2,-1,0,1,2,3,4,5,6,7,8,9,10,11,12,13,
    18,19,20,21, 34,35,36,37, 66,67,68,69,
    130,131,132,133, 258,259,260,261, 514,515,516,517,
    1026,1027,1028,1029
};

// TIDX[ei][j] = slot t (index into OFF) with OFF[t] = EREL[ei] + j, or -1
__device__ constexpr int TIDX[45][4] = {
    {-1,-1,-1, 0}, {-1,-1, 0, 1}, {-1, 0, 1, 2}, { 0, 1, 2, 3},
    { 1, 2, 3, 4}, { 2, 3, 4, 5}, { 3, 4, 5, 6}, { 4, 5, 6, 7},
    { 5, 6, 7,-1}, { 6, 7,-1, 8}, { 7,-1, 8,-1}, {-1, 8,-1,-1},
    { 8,-1,-1,-1}, {-1,-1,-1, 9}, {-1,-1, 9,-1}, {-1, 9,-1,-1},
    { 9,-1,-1,-1},
    {-1,-1,-1,10}, {-1,-1,10,-1}, {-1,10,-1,-1}, {10,-1,-1,-1},
    {-1,-1,-1,11}, {-1,-1,11,-1}, {-1,11,-1,-1}, {11,-1,-1,-1},
    {-1,-1,-1,12}, {-1,-1,12,-1}, {-1,12,-1,-1}, {12,-1,-1,-1},
    {-1,-1,-1,13}, {-1,-1,13,-1}, {-1,13,-1,-1}, {13,-1,-1,-1},
    {-1,-1,-1,14}, {-1,-1,14,-1}, {-1,14,-1,-1}, {14,-1,-1,-1},
    {-1,-1,-1,15}, {-1,-1,15,-1}, {-1,15,-1,-1}, {15,-1,-1,-1},
    {-1,-1,-1,16}, {-1,-1,16,-1}, {-1,16,-1,-1}, {16,-1,-1,-1}
};

// Transpose-reduce of 8 values over a 16-lane half: lane u ends holding the
// full 16-lane sum of value index (u>>1)&7 (duplicated in lane pairs). 8 SHFLs.
__device__ __forceinline__ float txr8(const float* v, int lane) {
    const unsigned FULL = 0xffffffffu;
    const bool b8 = (lane & 8) != 0;
    float w[4];
    #pragma unroll
    for (int i = 0; i < 4; i++) {
        float own = b8 ? v[i + 4] : v[i];
        float oth = b8 ? v[i] : v[i + 4];
        w[i] = own + __shfl_xor_sync(FULL, oth, 8);
    }
    const bool b4 = (lane & 4) != 0;
    float x[2];
    #pragma unroll
    for (int i = 0; i < 2; i++) {
        float own = b4 ? w[i + 2] : w[i];
        float oth = b4 ? w[i] : w[i + 2];
        x[i] = own + __shfl_xor_sync(FULL, oth, 4);
    }
    const bool b2 = (lane & 2) != 0;
    float own = b2 ? x[1] : x[0];
    float oth = b2 ? x[0] : x[1];
    float y = own + __shfl_xor_sync(FULL, oth, 2);
    y += __shfl_xor_sync(FULL, y, 1);   // bit0 partner holds the same index
    return y;
}

// One 4-query group (R8 body, proven correct at 72 regs).
__device__ __forceinline__ void do_group(
    const float* __restrict__ Q, const float* __restrict__ K,
    const float* __restrict__ V, float* __restrict__ O,
    int l0, int bhbase, int sub, int lane)
{
    const unsigned FULL = 0xffffffffu;
    const int rbase = bhbase + l0 * ROWSTR + sub * 4;

    float4 q0 = *reinterpret_cast<const float4*>(Q + rbase);
    float4 q1 = *reinterpret_cast<const float4*>(Q + rbase + ROWSTR);
    float4 q2 = *reinterpret_cast<const float4*>(Q + rbase + 2 * ROWSTR);
    float4 q3 = *reinterpret_cast<const float4*>(Q + rbase + 3 * ROWSTR);

    const int slot = (sub >> 1) & 7;
    const int offlo = slot;
    const int offhi = (1 << (slot + 3)) + 5;         // 13,21,...,1029
    const int halfbase = lane & 16;

    float ejlo[4], ejhi[4], e8r[4], inv[4];

    // ---------- Phase 1a: rows e=-3..9 -> slots 0..8 ----------
    {
        float slo[4][8];
        float s8[4];
        #pragma unroll
        for (int ei = 0; ei < 13; ei++) {
            const int e = EREL[ei];
            const bool ok = (l0 >= e);
            const int addr = ok ? (rbase - e * ROWSTR) : rbase;
            const float4 k = *reinterpret_cast<const float4*>(K + addr);
            #pragma unroll
            for (int j = 0; j < 4; j++) {
                const int t = TIDX[ei][j];
                if (t >= 0) {
                    const float4 qq = (j == 0) ? q0 : (j == 1) ? q1 : (j == 2) ? q2 : q3;
                    float p = qq.x * k.x;
                    p = fmaf(qq.y, k.y, p);
                    p = fmaf(qq.z, k.z, p);
                    p = fmaf(qq.w, k.w, p);
                    if (t < 8) slo[j][t] = p;
                    else       s8[j] = p;
                }
            }
        }
        #pragma unroll
        for (int j = 0; j < 4; j++) {
            float zlo = txr8(&slo[j][0], lane);
            float z8  = s8[j];
            z8 += __shfl_xor_sync(FULL, z8, 8);
            z8 += __shfl_xor_sync(FULL, z8, 4);
            z8 += __shfl_xor_sync(FULL, z8, 2);
            z8 += __shfl_xor_sync(FULL, z8, 1);
            ejlo[j] = (l0 + j >= offlo) ? __expf(zlo * SCALE) : 0.f;
            e8r[j]  = (l0 + j >= 9)     ? __expf(z8  * SCALE) : 0.f;
        }
    }

    // ---------- Phase 1b: rows e=10..1029 -> slots 9..16 ----------
    {
        float shi[4][8];
        #pragma unroll
        for (int ei = 13; ei < 45; ei++) {
            const int e = EREL[ei];
            const bool ok = (l0 >= e);
            const int addr = ok ? (rbase - e * ROWSTR) : rbase;
            const float4 k = *reinterpret_cast<const float4*>(K + addr);
            #pragma unroll
            for (int j = 0; j < 4; j++) {
                const int t = TIDX[ei][j];
                if (t >= 0) {
                    const float4 qq = (j == 0) ? q0 : (j == 1) ? q1 : (j == 2) ? q2 : q3;
                    float p = qq.x * k.x;
                    p = fmaf(qq.y, k.y, p);
                    p = fmaf(qq.z, k.z, p);
                    p = fmaf(qq.w, k.w, p);
                    shi[j][t - 9] = p;
                }
            }
        }
        #pragma unroll
        for (int j = 0; j < 4; j++) {
            float zhi = txr8(&shi[j][0], lane);
            ejhi[j] = (l0 + j >= offhi) ? __expf(zhi * SCALE) : 0.f;
            float sm = ejlo[j] + ejhi[j];
            sm += __shfl_xor_sync(FULL, sm, 2);
            sm += __shfl_xor_sync(FULL, sm, 4);
            sm += __shfl_xor_sync(FULL, sm, 8);
            inv[j] = __fdividef(1.f, sm + e8r[j]);
        }
    }

    // ---------- Phase 3: weighted V accumulation ----------
    float4 a0 = make_float4(0.f, 0.f, 0.f, 0.f);
    float4 a1 = a0, a2 = a0, a3 = a0;

    #pragma unroll
    for (int ei = 0; ei < 45; ei++) {
        const int e = EREL[ei];
        const bool ok = (l0 >= e);
        const int addr = ok ? (rbase - e * ROWSTR) : rbase;
        const float4 v = *reinterpret_cast<const float4*>(V + addr);
        #pragma unroll
        for (int j = 0; j < 4; j++) {
            const int t = TIDX[ei][j];
            if (t >= 0) {
                float w;
                if (t == 8)      w = e8r[j];
                else if (t < 8)  w = __shfl_sync(FULL, ejlo[j], halfbase + 2 * t);
                else             w = __shfl_sync(FULL, ejhi[j], halfbase + 2 * (t - 9));
                float4& a = (j == 0) ? a0 : (j == 1) ? a1 : (j == 2) ? a2 : a3;
                a.x = fmaf(w, v.x, a.x);
                a.y = fmaf(w, v.y, a.y);
                a.z = fmaf(w, v.z, a.z);
                a.w = fmaf(w, v.w, a.w);
            }
        }
    }

    a0.x *= inv[0]; a0.y *= inv[0]; a0.z *= inv[0]; a0.w *= inv[0];
    a1.x *= inv[1]; a1.y *= inv[1]; a1.z *= inv[1]; a1.w *= inv[1];
    a2.x *= inv[2]; a2.y *= inv[2]; a2.z *= inv[2]; a2.w *= inv[2];
    a3.x *= inv[3]; a3.y *= inv[3]; a3.z *= inv[3]; a3.w *= inv[3];

    *reinterpret_cast<float4*>(O + rbase)              = a0;
    *reinterpret_cast<float4*>(O + rbase + ROWSTR)     = a1;
    *reinterpret_cast<float4*>(O + rbase + 2 * ROWSTR) = a2;
    *reinterpret_cast<float4*>(O + rbase + 3 * ROWSTR) = a3;
}

__global__ __launch_bounds__(128, 7) void sparse_attn_span(
    const float* __restrict__ Q,
    const float* __restrict__ K,
    const float* __restrict__ V,
    float* __restrict__ O)
{
    const int tid  = threadIdx.x;
    const int warp = tid >> 5;
    const int lane = tid & 31;
    const int half = lane >> 4;
    const int sub  = lane & 15;

    // 256 CTAs: each owns 256 consecutive queries of one (b,h),
    // processed as 8 chunks of 32 in ASCENDING order (L1 temporal reuse:
    // a row's window fetch is re-used at its d=21/37/69/133 far uses).
    const int cta  = blockIdx.x;
    const int span = cta & 7;                    // 8 spans of 256 queries
    const int bh   = cta >> 3;
    const int h    = bh & 7;
    const int b    = bh >> 3;

    const int bhbase = (b * Lc) * ROWSTR + h * 64;
    const int lspan  = span * 256;

    #pragma unroll 1
    for (int it = 0; it < ITERS; it++) {
        const int l0 = lspan + it * 32 + warp * 8 + half * 4;
        do_group(Q, K, V, O, l0, bhbase, sub, lane);
    }
}

extern "C" void kernel_launch(void* const* d_in, const int* in_sizes, int n_in,
                              void* d_out, int out_size)
{
    const float* Q = (const float*)d_in[0];
    const float* K = (const float*)d_in[1];
    const float* V = (const float*)d_in[2];
    float* O = (float*)d_out;

    const int nblocks = Bc * Hc * (Lc / 256); // 256 CTAs
    sparse_attn_span<<<nblocks, 128>>>(Q, K, V, O);
}

// round 13
// speedup vs baseline: 1.9374x; 1.9374x over previous
#include <cuda_runtime.h>

// Log-sparse causal attention, B=4, L=2048, H=8, E=D=64, fp32.
// Query l attends keys l-d for d in OFF (17 offsets), d <= l.
// Half-warp (16 lanes) processes QG=4 consecutive queries, sharing K/V row
// loads across the group (45 distinct rows). Score array split lo(8)/s8/hi(8)
// keeps regs ~72. Loads UNCONDITIONAL clamped-address (R6 lesson).
// R13: CTA = 256 threads = 64 consecutive queries, ~3 CTAs/SM resident ->
// per-SM L1 working set small enough that window-row fetches are re-hit at
// their d=21/37/69/133 far uses by neighboring warps, cutting L2->L1 refetch
// (the measured bottleneck behind the 25us plateau).

constexpr int Bc = 4, Lc = 2048, Hc = 8;
constexpr float SCALE = 0.125f;      // 1/sqrt(64)
constexpr int ROWSTR = Hc * 64;      // 512 elements per l-step

// 45 distinct relative rows e (row = l0 - e) covering all (j in 0..3, d in OFF)
__device__ constexpr int EREL[45] = {
    -3,-2,-1,0,1,2,3,4,5,6,7,8,9,10,11,12,13,
    18,19,20,21, 34,35,36,37, 66,67,68,69,
    130,131,132,133, 258,259,260,261, 514,515,516,517,
    1026,1027,1028,1029
};

// TIDX[ei][j] = slot t (index into OFF) with OFF[t] = EREL[ei] + j, or -1
__device__ constexpr int TIDX[45][4] = {
    {-1,-1,-1, 0}, {-1,-1, 0, 1}, {-1, 0, 1, 2}, { 0, 1, 2, 3},
    { 1, 2, 3, 4}, { 2, 3, 4, 5}, { 3, 4, 5, 6}, { 4, 5, 6, 7},
    { 5, 6, 7,-1}, { 6, 7,-1, 8}, { 7,-1, 8,-1}, {-1, 8,-1,-1},
    { 8,-1,-1,-1}, {-1,-1,-1, 9}, {-1,-1, 9,-1}, {-1, 9,-1,-1},
    { 9,-1,-1,-1},
    {-1,-1,-1,10}, {-1,-1,10,-1}, {-1,10,-1,-1}, {10,-1,-1,-1},
    {-1,-1,-1,11}, {-1,-1,11,-1}, {-1,11,-1,-1}, {11,-1,-1,-1},
    {-1,-1,-1,12}, {-1,-1,12,-1}, {-1,12,-1,-1}, {12,-1,-1,-1},
    {-1,-1,-1,13}, {-1,-1,13,-1}, {-1,13,-1,-1}, {13,-1,-1,-1},
    {-1,-1,-1,14}, {-1,-1,14,-1}, {-1,14,-1,-1}, {14,-1,-1,-1},
    {-1,-1,-1,15}, {-1,-1,15,-1}, {-1,15,-1,-1}, {15,-1,-1,-1},
    {-1,-1,-1,16}, {-1,-1,16,-1}, {-1,16,-1,-1}, {16,-1,-1,-1}
};

// Transpose-reduce of 8 values over a 16-lane half: lane u ends holding the
// full 16-lane sum of value index (u>>1)&7 (duplicated in lane pairs). 8 SHFLs.
__device__ __forceinline__ float txr8(const float* v, int lane) {
    const unsigned FULL = 0xffffffffu;
    const bool b8 = (lane & 8) != 0;
    float w[4];
    #pragma unroll
    for (int i = 0; i < 4; i++) {
        float own = b8 ? v[i + 4] : v[i];
        float oth = b8 ? v[i] : v[i + 4];
        w[i] = own + __shfl_xor_sync(FULL, oth, 8);
    }
    const bool b4 = (lane & 4) != 0;
    float x[2];
    #pragma unroll
    for (int i = 0; i < 2; i++) {
        float own = b4 ? w[i + 2] : w[i];
        float oth = b4 ? w[i] : w[i + 2];
        x[i] = own + __shfl_xor_sync(FULL, oth, 4);
    }
    const bool b2 = (lane & 2) != 0;
    float own = b2 ? x[1] : x[0];
    float oth = b2 ? x[0] : x[1];
    float y = own + __shfl_xor_sync(FULL, oth, 2);
    y += __shfl_xor_sync(FULL, y, 1);   // bit0 partner holds the same index
    return y;
}

__global__ __launch_bounds__(256, 3) void sparse_attn_cta64(
    const float* __restrict__ Q,
    const float* __restrict__ K,
    const float* __restrict__ V,
    float* __restrict__ O)
{
    const unsigned FULL = 0xffffffffu;
    const int tid  = threadIdx.x;
    const int warp = tid >> 5;       // 0..7
    const int lane = tid & 31;
    const int half = lane >> 4;
    const int sub  = lane & 15;      // dim slice: floats [4*sub, 4*sub+4)

    // CTA = 64 consecutive queries of one (b,h). grid = 4*8*32 = 1024
    const int cta   = blockIdx.x;
    const int chunk = cta & 31;
    const int bh    = cta >> 5;
    const int h     = bh & 7;
    const int b     = bh >> 3;

    const int l0 = chunk * 64 + warp * 8 + half * 4;   // first of 4 queries

    const int rbase = ((b * Lc + l0) * Hc + h) * 64 + sub * 4;

    // load the 4 query rows
    float4 q0 = *reinterpret_cast<const float4*>(Q + rbase);
    float4 q1 = *reinterpret_cast<const float4*>(Q + rbase + ROWSTR);
    float4 q2 = *reinterpret_cast<const float4*>(Q + rbase + 2 * ROWSTR);
    float4 q3 = *reinterpret_cast<const float4*>(Q + rbase + 3 * ROWSTR);

    const int slot = (sub >> 1) & 7;                 // my lane pair's value index
    const int offlo = slot;                          // OFF[slot] for lo slots
    const int offhi = (1 << (slot + 3)) + 5;         // OFF[slot+9]: 13,21,...,1029
    const int halfbase = lane & 16;

    float ejlo[4], ejhi[4], e8r[4], inv[4];

    // ---------- Phase 1a: rows e=-3..9 -> slots 0..8 ----------
    {
        float slo[4][8];
        float s8[4];
        #pragma unroll
        for (int ei = 0; ei < 13; ei++) {
            const int e = EREL[ei];
            const bool ok = (l0 >= e);
            const int addr = ok ? (rbase - e * ROWSTR) : rbase;  // clamped
            const float4 k = *reinterpret_cast<const float4*>(K + addr);
            #pragma unroll
            for (int j = 0; j < 4; j++) {
                const int t = TIDX[ei][j];
                if (t >= 0) {
                    const float4 qq = (j == 0) ? q0 : (j == 1) ? q1 : (j == 2) ? q2 : q3;
                    float p = qq.x * k.x;
                    p = fmaf(qq.y, k.y, p);
                    p = fmaf(qq.z, k.z, p);
                    p = fmaf(qq.w, k.w, p);
                    if (t < 8) slo[j][t] = p;
                    else       s8[j] = p;            // t == 8 exactly
                }
            }
        }
        #pragma unroll
        for (int j = 0; j < 4; j++) {
            float zlo = txr8(&slo[j][0], lane);
            float z8  = s8[j];
            z8 += __shfl_xor_sync(FULL, z8, 8);
            z8 += __shfl_xor_sync(FULL, z8, 4);
            z8 += __shfl_xor_sync(FULL, z8, 2);
            z8 += __shfl_xor_sync(FULL, z8, 1);
            ejlo[j] = (l0 + j >= offlo) ? __expf(zlo * SCALE) : 0.f;
            e8r[j]  = (l0 + j >= 9)     ? __expf(z8  * SCALE) : 0.f;
        }
    }

    // ---------- Phase 1b: rows e=10..1029 -> slots 9..16 ----------
    {
        float shi[4][8];
        #pragma unroll
        for (int ei = 13; ei < 45; ei++) {
            const int e = EREL[ei];
            const bool ok = (l0 >= e);
            const int addr = ok ? (rbase - e * ROWSTR) : rbase;  // clamped
            const float4 k = *reinterpret_cast<const float4*>(K + addr);
            #pragma unroll
            for (int j = 0; j < 4; j++) {
                const int t = TIDX[ei][j];
                if (t >= 0) {
                    const float4 qq = (j == 0) ? q0 : (j == 1) ? q1 : (j == 2) ? q2 : q3;
                    float p = qq.x * k.x;
                    p = fmaf(qq.y, k.y, p);
                    p = fmaf(qq.z, k.z, p);
                    p = fmaf(qq.w, k.w, p);
                    shi[j][t - 9] = p;
                }
            }
        }
        #pragma unroll
        for (int j = 0; j < 4; j++) {
            float zhi = txr8(&shi[j][0], lane);
            ejhi[j] = (l0 + j >= offhi) ? __expf(zhi * SCALE) : 0.f;
            // denominator: lanes u,u^1 hold duplicates -> butterfly {2,4,8}
            float sm = ejlo[j] + ejhi[j];
            sm += __shfl_xor_sync(FULL, sm, 2);
            sm += __shfl_xor_sync(FULL, sm, 4);
            sm += __shfl_xor_sync(FULL, sm, 8);
            inv[j] = __fdividef(1.f, sm + e8r[j]);
        }
    }

    // ---------- Phase 3: weighted V accumulation (clamped loads) ----------
    float4 a0 = make_float4(0.f, 0.f, 0.f, 0.f);
    float4 a1 = a0, a2 = a0, a3 = a0;

    #pragma unroll
    for (int ei = 0; ei < 45; ei++) {
        const int e = EREL[ei];
        const bool ok = (l0 >= e);
        const int addr = ok ? (rbase - e * ROWSTR) : rbase;  // clamped
        const float4 v = *reinterpret_cast<const float4*>(V + addr);
        #pragma unroll
        for (int j = 0; j < 4; j++) {
            const int t = TIDX[ei][j];
            if (t >= 0) {
                float w;
                if (t == 8)      w = e8r[j];                                  // replicated
                else if (t < 8)  w = __shfl_sync(FULL, ejlo[j], halfbase + 2 * t);
                else             w = __shfl_sync(FULL, ejhi[j], halfbase + 2 * (t - 9));
                // w == 0 exactly for invalid uses -> clamped v is harmless
                float4& a = (j == 0) ? a0 : (j == 1) ? a1 : (j == 2) ? a2 : a3;
                a.x = fmaf(w, v.x, a.x);
                a.y = fmaf(w, v.y, a.y);
                a.z = fmaf(w, v.z, a.z);
                a.w = fmaf(w, v.w, a.w);
            }
        }
    }

    a0.x *= inv[0]; a0.y *= inv[0]; a0.z *= inv[0]; a0.w *= inv[0];
    a1.x *= inv[1]; a1.y *= inv[1]; a1.z *= inv[1]; a1.w *= inv[1];
    a2.x *= inv[2]; a2.y *= inv[2]; a2.z *= inv[2]; a2.w *= inv[2];
    a3.x *= inv[3]; a3.y *= inv[3]; a3.z *= inv[3]; a3.w *= inv[3];

    *reinterpret_cast<float4*>(O + rbase)              = a0;
    *reinterpret_cast<float4*>(O + rbase + ROWSTR)     = a1;
    *reinterpret_cast<float4*>(O + rbase + 2 * ROWSTR) = a2;
    *reinterpret_cast<float4*>(O + rbase + 3 * ROWSTR) = a3;
}

extern "C" void kernel_launch(void* const* d_in, const int* in_sizes, int n_in,
                              void* d_out, int out_size)
{
    const float* Q = (const float*)d_in[0];
    const float* K = (const float*)d_in[1];
    const float* V = (const float*)d_in[2];
    float* O = (float*)d_out;

    const int nblocks = Bc * Hc * (Lc / 64); // 1024 CTAs of 256 threads
    sparse_attn_cta64<<<nblocks, 256>>>(Q, K, V, O);
}

// round 14
// speedup vs baseline: 2.0233x; 1.0443x over previous
#include <cuda_runtime.h>

// Log-sparse causal attention, B=4, L=2048, H=8, E=D=64, fp32.
// Query l attends keys l-d for d in OFF (17 offsets), d <= l.
// Half-warp (16 lanes) processes QG=4 consecutive queries, sharing K/V row
// loads across the group (45 distinct rows). Score array split lo(8)/s8/hi(8).
// R14: first 12 V rows are prefetched into registers right after the phase-1b
// K loads, so their latency is hidden behind the phase-2 shuffle/exp chain
// (previously the memory system idled there). launch_bounds(128,5) gives
// ptxas the registers to keep them live.

constexpr int Bc = 4, Lc = 2048, Hc = 8;
constexpr float SCALE = 0.125f;      // 1/sqrt(64)
constexpr int ROWSTR = Hc * 64;      // 512 elements per l-step
constexpr int NPRE = 12;             // V rows prefetched across phase 2

// 45 distinct relative rows e (row = l0 - e) covering all (j in 0..3, d in OFF)
__device__ constexpr int EREL[45] = {
    -3,-2,-1,0,1,2,3,4,5,6,7,8,9,10,11,12,13,
    18,19,20,21, 34,35,36,37, 66,67,68,69,
    130,131,132,133, 258,259,260,261, 514,515,516,517,
    1026,1027,1028,1029
};

// TIDX[ei][j] = slot t (index into OFF) with OFF[t] = EREL[ei] + j, or -1
__device__ constexpr int TIDX[45][4] = {
    {-1,-1,-1, 0}, {-1,-1, 0, 1}, {-1, 0, 1, 2}, { 0, 1, 2, 3},
    { 1, 2, 3, 4}, { 2, 3, 4, 5}, { 3, 4, 5, 6}, { 4, 5, 6, 7},
    { 5, 6, 7,-1}, { 6, 7,-1, 8}, { 7,-1, 8,-1}, {-1, 8,-1,-1},
    { 8,-1,-1,-1}, {-1,-1,-1, 9}, {-1,-1, 9,-1}, {-1, 9,-1,-1},
    { 9,-1,-1,-1},
    {-1,-1,-1,10}, {-1,-1,10,-1}, {-1,10,-1,-1}, {10,-1,-1,-1},
    {-1,-1,-1,11}, {-1,-1,11,-1}, {-1,11,-1,-1}, {11,-1,-1,-1},
    {-1,-1,-1,12}, {-1,-1,12,-1}, {-1,12,-1,-1}, {12,-1,-1,-1},
    {-1,-1,-1,13}, {-1,-1,13,-1}, {-1,13,-1,-1}, {13,-1,-1,-1},
    {-1,-1,-1,14}, {-1,-1,14,-1}, {-1,14,-1,-1}, {14,-1,-1,-1},
    {-1,-1,-1,15}, {-1,-1,15,-1}, {-1,15,-1,-1}, {15,-1,-1,-1},
    {-1,-1,-1,16}, {-1,-1,16,-1}, {-1,16,-1,-1}, {16,-1,-1,-1}
};

// Transpose-reduce of 8 values over a 16-lane half: lane u ends holding the
// full 16-lane sum of value index (u>>1)&7 (duplicated in lane pairs). 8 SHFLs.
__device__ __forceinline__ float txr8(const float* v, int lane) {
    const unsigned FULL = 0xffffffffu;
    const bool b8 = (lane & 8) != 0;
    float w[4];
    #pragma unroll
    for (int i = 0; i < 4; i++) {
        float own = b8 ? v[i + 4] : v[i];
        float oth = b8 ? v[i] : v[i + 4];
        w[i] = own + __shfl_xor_sync(FULL, oth, 8);
    }
    const bool b4 = (lane & 4) != 0;
    float x[2];
    #pragma unroll
    for (int i = 0; i < 2; i++) {
        float own = b4 ? w[i + 2] : w[i];
        float oth = b4 ? w[i] : w[i + 2];
        x[i] = own + __shfl_xor_sync(FULL, oth, 4);
    }
    const bool b2 = (lane & 2) != 0;
    float own = b2 ? x[1] : x[0];
    float oth = b2 ? x[0] : x[1];
    float y = own + __shfl_xor_sync(FULL, oth, 2);
    y += __shfl_xor_sync(FULL, y, 1);   // bit0 partner holds the same index
    return y;
}

__global__ __launch_bounds__(128, 5) void sparse_attn_pf(
    const float* __restrict__ Q,
    const float* __restrict__ K,
    const float* __restrict__ V,
    float* __restrict__ O)
{
    const unsigned FULL = 0xffffffffu;
    const int tid  = threadIdx.x;
    const int warp = tid >> 5;
    const int lane = tid & 31;
    const int half = lane >> 4;
    const int sub  = lane & 15;      // dim slice: floats [4*sub, 4*sub+4)

    // CTA = 32 consecutive queries of one (b,h). grid = 4*8*64 = 2048
    const int cta   = blockIdx.x;
    const int chunk = cta & 63;
    const int bh    = cta >> 6;
    const int h     = bh & 7;
    const int b     = bh >> 3;

    const int l0 = chunk * 32 + warp * 8 + half * 4;   // first of 4 queries

    const int rbase = ((b * Lc + l0) * Hc + h) * 64 + sub * 4;

    // load the 4 query rows
    float4 q0 = *reinterpret_cast<const float4*>(Q + rbase);
    float4 q1 = *reinterpret_cast<const float4*>(Q + rbase + ROWSTR);
    float4 q2 = *reinterpret_cast<const float4*>(Q + rbase + 2 * ROWSTR);
    float4 q3 = *reinterpret_cast<const float4*>(Q + rbase + 3 * ROWSTR);

    const int slot = (sub >> 1) & 7;                 // my lane pair's value index
    const int offlo = slot;                          // OFF[slot] for lo slots
    const int offhi = (1 << (slot + 3)) + 5;         // OFF[slot+9]: 13,21,...,1029
    const int halfbase = lane & 16;

    float ejlo[4], ejhi[4], e8r[4], inv[4];
    float4 vpre[NPRE];                               // prefetched V rows 0..NPRE-1

    // ---------- Phase 1a: rows e=-3..9 -> slots 0..8 ----------
    float slo[4][8];
    float s8[4];
    #pragma unroll
    for (int ei = 0; ei < 13; ei++) {
        const int e = EREL[ei];
        const bool ok = (l0 >= e);
        const int addr = ok ? (rbase - e * ROWSTR) : rbase;  // clamped
        const float4 k = *reinterpret_cast<const float4*>(K + addr);
        #pragma unroll
        for (int j = 0; j < 4; j++) {
            const int t = TIDX[ei][j];
            if (t >= 0) {
                const float4 qq = (j == 0) ? q0 : (j == 1) ? q1 : (j == 2) ? q2 : q3;
                float p = qq.x * k.x;
                p = fmaf(qq.y, k.y, p);
                p = fmaf(qq.z, k.z, p);
                p = fmaf(qq.w, k.w, p);
                if (t < 8) slo[j][t] = p;
                else       s8[j] = p;            // t == 8 exactly
            }
        }
    }

    // ---------- Phase 1b K loads: rows e=10..1029 -> slots 9..16 ----------
    float shi[4][8];
    #pragma unroll
    for (int ei = 13; ei < 45; ei++) {
        const int e = EREL[ei];
        const bool ok = (l0 >= e);
        const int addr = ok ? (rbase - e * ROWSTR) : rbase;  // clamped
        const float4 k = *reinterpret_cast<const float4*>(K + addr);
        #pragma unroll
        for (int j = 0; j < 4; j++) {
            const int t = TIDX[ei][j];
            if (t >= 0) {
                const float4 qq = (j == 0) ? q0 : (j == 1) ? q1 : (j == 2) ? q2 : q3;
                float p = qq.x * k.x;
                p = fmaf(qq.y, k.y, p);
                p = fmaf(qq.z, k.z, p);
                p = fmaf(qq.w, k.w, p);
                shi[j][t - 9] = p;
            }
        }
    }

    // ---------- V prefetch: independent of phase 2; latency hides under it ----
    #pragma unroll
    for (int ei = 0; ei < NPRE; ei++) {
        const int e = EREL[ei];
        const int addr = (l0 >= e) ? (rbase - e * ROWSTR) : rbase;  // clamped
        vpre[ei] = *reinterpret_cast<const float4*>(V + addr);
    }

    // ---------- Phase 2: reductions + exp (no max pass) ----------
    #pragma unroll
    for (int j = 0; j < 4; j++) {
        float zlo = txr8(&slo[j][0], lane);
        float z8  = s8[j];
        z8 += __shfl_xor_sync(FULL, z8, 8);
        z8 += __shfl_xor_sync(FULL, z8, 4);
        z8 += __shfl_xor_sync(FULL, z8, 2);
        z8 += __shfl_xor_sync(FULL, z8, 1);
        ejlo[j] = (l0 + j >= offlo) ? __expf(zlo * SCALE) : 0.f;
        e8r[j]  = (l0 + j >= 9)     ? __expf(z8  * SCALE) : 0.f;
    }
    #pragma unroll
    for (int j = 0; j < 4; j++) {
        float zhi = txr8(&shi[j][0], lane);
        ejhi[j] = (l0 + j >= offhi) ? __expf(zhi * SCALE) : 0.f;
        // denominator: lanes u,u^1 hold duplicates -> butterfly {2,4,8}
        float sm = ejlo[j] + ejhi[j];
        sm += __shfl_xor_sync(FULL, sm, 2);
        sm += __shfl_xor_sync(FULL, sm, 4);
        sm += __shfl_xor_sync(FULL, sm, 8);
        inv[j] = __fdividef(1.f, sm + e8r[j]);
    }

    // ---------- Phase 3: weighted V accumulation (clamped loads) ----------
    float4 a0 = make_float4(0.f, 0.f, 0.f, 0.f);
    float4 a1 = a0, a2 = a0, a3 = a0;

    #pragma unroll
    for (int ei = 0; ei < 45; ei++) {
        const int e = EREL[ei];
        float4 v;
        if (ei < NPRE) {
            v = vpre[ei];
        } else {
            const int addr = (l0 >= e) ? (rbase - e * ROWSTR) : rbase;  // clamped
            v = *reinterpret_cast<const float4*>(V + addr);
        }
        #pragma unroll
        for (int j = 0; j < 4; j++) {
            const int t = TIDX[ei][j];
            if (t >= 0) {
                float w;
                if (t == 8)      w = e8r[j];                                  // replicated
                else if (t < 8)  w = __shfl_sync(FULL, ejlo[j], halfbase + 2 * t);
                else             w = __shfl_sync(FULL, ejhi[j], halfbase + 2 * (t - 9));
                // w == 0 exactly for invalid uses -> clamped v is harmless
                float4& a = (j == 0) ? a0 : (j == 1) ? a1 : (j == 2) ? a2 : a3;
                a.x = fmaf(w, v.x, a.x);
                a.y = fmaf(w, v.y, a.y);
                a.z = fmaf(w, v.z, a.z);
                a.w = fmaf(w, v.w, a.w);
            }
        }
    }

    a0.x *= inv[0]; a0.y *= inv[0]; a0.z *= inv[0]; a0.w *= inv[0];
    a1.x *= inv[1]; a1.y *= inv[1]; a1.z *= inv[1]; a1.w *= inv[1];
    a2.x *= inv[2]; a2.y *= inv[2]; a2.z *= inv[2]; a2.w *= inv[2];
    a3.x *= inv[3]; a3.y *= inv[3]; a3.z *= inv[3]; a3.w *= inv[3];

    *reinterpret_cast<float4*>(O + rbase)              = a0;
    *reinterpret_cast<float4*>(O + rbase + ROWSTR)     = a1;
    *reinterpret_cast<float4*>(O + rbase + 2 * ROWSTR) = a2;
    *reinterpret_cast<float4*>(O + rbase + 3 * ROWSTR) = a3;
}

extern "C" void kernel_launch(void* const* d_in, const int* in_sizes, int n_in,
                              void* d_out, int out_size)
{
    const float* Q = (const float*)d_in[0];
    const float* K = (const float*)d_in[1];
    const float* V = (const float*)d_in[2];
    float* O = (float*)d_out;

    const int nblocks = Bc * Hc * (Lc / 32); // 2048
    sparse_attn_pf<<<nblocks, 128>>>(Q, K, V, O);
}

// round 15
// speedup vs baseline: 2.1368x; 1.0561x over previous
#include <cuda_runtime.h>

// Log-sparse causal attention, B=4, L=2048, H=8, E=D=64, fp32.
// Query l attends keys l-d for d in OFF (17 offsets), d <= l.
// R8 champion body (half-warp QG=4, split score array, 72 regs, clamped
// unconditional loads) + R15: all dot products and V accumulation use packed
// f32x2 FMA (PTX mul.rn.f32x2 / fma.rn.f32x2) to cut FMA instruction count
// ~2x (ptxas never emits FFMA2 on its own).

constexpr int Bc = 4, Lc = 2048, Hc = 8;
constexpr float SCALE = 0.125f;      // 1/sqrt(64)
constexpr int ROWSTR = Hc * 64;      // 512 elements per l-step

typedef unsigned long long u64;

// ---- packed f32x2 helpers (sm_100+) ----
__device__ __forceinline__ u64 f2mul(u64 a, u64 b) {
    u64 d; asm("mul.rn.f32x2 %0, %1, %2;" : "=l"(d) : "l"(a), "l"(b)); return d;
}
__device__ __forceinline__ u64 f2fma(u64 a, u64 b, u64 c) {
    u64 d; asm("fma.rn.f32x2 %0, %1, %2, %3;" : "=l"(d) : "l"(a), "l"(b), "l"(c)); return d;
}
__device__ __forceinline__ float f2hsum(u64 p) {
    unsigned lo, hi;
    asm("mov.b64 {%0, %1}, %2;" : "=r"(lo), "=r"(hi) : "l"(p));
    return __uint_as_float(lo) + __uint_as_float(hi);
}
__device__ __forceinline__ u64 f2dup(float x) {
    u64 d; unsigned xb = __float_as_uint(x);
    asm("mov.b64 %0, {%1, %1};" : "=l"(d) : "r"(xb)); return d;
}

// 45 distinct relative rows e (row = l0 - e) covering all (j in 0..3, d in OFF)
__device__ constexpr int EREL[45] = {
    -3,-2,-1,0,1,2,3,4,5,6,7,8,9,10,11,12,13,
    18,19,20,21, 34,35,36,37, 66,67,68,69,
    130,131,132,133, 258,259,260,261, 514,515,516,517,
    1026,1027,1028,1029
};

// TIDX[ei][j] = slot t (index into OFF) with OFF[t] = EREL[ei] + j, or -1
__device__ constexpr int TIDX[45][4] = {
    {-1,-1,-1, 0}, {-1,-1, 0, 1}, {-1, 0, 1, 2}, { 0, 1, 2, 3},
    { 1, 2, 3, 4}, { 2, 3, 4, 5}, { 3, 4, 5, 6}, { 4, 5, 6, 7},
    { 5, 6, 7,-1}, { 6, 7,-1, 8}, { 7,-1, 8,-1}, {-1, 8,-1,-1},
    { 8,-1,-1,-1}, {-1,-1,-1, 9}, {-1,-1, 9,-1}, {-1, 9,-1,-1},
    { 9,-1,-1,-1},
    {-1,-1,-1,10}, {-1,-1,10,-1}, {-1,10,-1,-1}, {10,-1,-1,-1},
    {-1,-1,-1,11}, {-1,-1,11,-1}, {-1,11,-1,-1}, {11,-1,-1,-1},
    {-1,-1,-1,12}, {-1,-1,12,-1}, {-1,12,-1,-1}, {12,-1,-1,-1},
    {-1,-1,-1,13}, {-1,-1,13,-1}, {-1,13,-1,-1}, {13,-1,-1,-1},
    {-1,-1,-1,14}, {-1,-1,14,-1}, {-1,14,-1,-1}, {14,-1,-1,-1},
    {-1,-1,-1,15}, {-1,-1,15,-1}, {-1,15,-1,-1}, {15,-1,-1,-1},
    {-1,-1,-1,16}, {-1,-1,16,-1}, {-1,16,-1,-1}, {16,-1,-1,-1}
};

// Transpose-reduce of 8 values over a 16-lane half: lane u ends holding the
// full 16-lane sum of value index (u>>1)&7 (duplicated in lane pairs). 8 SHFLs.
__device__ __forceinline__ float txr8(const float* v, int lane) {
    const unsigned FULL = 0xffffffffu;
    const bool b8 = (lane & 8) != 0;
    float w[4];
    #pragma unroll
    for (int i = 0; i < 4; i++) {
        float own = b8 ? v[i + 4] : v[i];
        float oth = b8 ? v[i] : v[i + 4];
        w[i] = own + __shfl_xor_sync(FULL, oth, 8);
    }
    const bool b4 = (lane & 4) != 0;
    float x[2];
    #pragma unroll
    for (int i = 0; i < 2; i++) {
        float own = b4 ? w[i + 2] : w[i];
        float oth = b4 ? w[i] : w[i + 2];
        x[i] = own + __shfl_xor_sync(FULL, oth, 4);
    }
    const bool b2 = (lane & 2) != 0;
    float own = b2 ? x[1] : x[0];
    float oth = b2 ? x[0] : x[1];
    float y = own + __shfl_xor_sync(FULL, oth, 2);
    y += __shfl_xor_sync(FULL, y, 1);   // bit0 partner holds the same index
    return y;
}

__global__ __launch_bounds__(128, 7) void sparse_attn_f32x2(
    const float* __restrict__ Q,
    const float* __restrict__ K,
    const float* __restrict__ V,
    float* __restrict__ O)
{
    const unsigned FULL = 0xffffffffu;
    const int tid  = threadIdx.x;
    const int warp = tid >> 5;
    const int lane = tid & 31;
    const int half = lane >> 4;
    const int sub  = lane & 15;      // dim slice: floats [4*sub, 4*sub+4)

    // CTA = 32 consecutive queries of one (b,h). grid = 4*8*64 = 2048
    const int cta   = blockIdx.x;
    const int chunk = cta & 63;
    const int bh    = cta >> 6;
    const int h     = bh & 7;
    const int b     = bh >> 3;

    const int l0 = chunk * 32 + warp * 8 + half * 4;   // first of 4 queries

    const int rbase = ((b * Lc + l0) * Hc + h) * 64 + sub * 4;

    // load the 4 query rows as packed f32x2 pairs
    ulonglong2 q0 = *reinterpret_cast<const ulonglong2*>(Q + rbase);
    ulonglong2 q1 = *reinterpret_cast<const ulonglong2*>(Q + rbase + ROWSTR);
    ulonglong2 q2 = *reinterpret_cast<const ulonglong2*>(Q + rbase + 2 * ROWSTR);
    ulonglong2 q3 = *reinterpret_cast<const ulonglong2*>(Q + rbase + 3 * ROWSTR);

    const int slot = (sub >> 1) & 7;                 // my lane pair's value index
    const int offlo = slot;                          // OFF[slot] for lo slots
    const int offhi = (1 << (slot + 3)) + 5;         // OFF[slot+9]: 13,21,...,1029
    const int halfbase = lane & 16;

    float ejlo[4], ejhi[4], e8r[4], inv[4];

    // ---------- Phase 1a: rows e=-3..9 -> slots 0..8 ----------
    {
        float slo[4][8];
        float s8[4];
        #pragma unroll
        for (int ei = 0; ei < 13; ei++) {
            const int e = EREL[ei];
            const bool ok = (l0 >= e);
            const int addr = ok ? (rbase - e * ROWSTR) : rbase;  // clamped
            const ulonglong2 k = *reinterpret_cast<const ulonglong2*>(K + addr);
            #pragma unroll
            for (int j = 0; j < 4; j++) {
                const int t = TIDX[ei][j];
                if (t >= 0) {
                    const ulonglong2 qq = (j == 0) ? q0 : (j == 1) ? q1 : (j == 2) ? q2 : q3;
                    const float p = f2hsum(f2fma(qq.y, k.y, f2mul(qq.x, k.x)));
                    if (t < 8) slo[j][t] = p;
                    else       s8[j] = p;            // t == 8 exactly
                }
            }
        }
        #pragma unroll
        for (int j = 0; j < 4; j++) {
            float zlo = txr8(&slo[j][0], lane);
            float z8  = s8[j];
            z8 += __shfl_xor_sync(FULL, z8, 8);
            z8 += __shfl_xor_sync(FULL, z8, 4);
            z8 += __shfl_xor_sync(FULL, z8, 2);
            z8 += __shfl_xor_sync(FULL, z8, 1);
            ejlo[j] = (l0 + j >= offlo) ? __expf(zlo * SCALE) : 0.f;
            e8r[j]  = (l0 + j >= 9)     ? __expf(z8  * SCALE) : 0.f;
        }
    }

    // ---------- Phase 1b: rows e=10..1029 -> slots 9..16 ----------
    {
        float shi[4][8];
        #pragma unroll
        for (int ei = 13; ei < 45; ei++) {
            const int e = EREL[ei];
            const bool ok = (l0 >= e);
            const int addr = ok ? (rbase - e * ROWSTR) : rbase;  // clamped
            const ulonglong2 k = *reinterpret_cast<const ulonglong2*>(K + addr);
            #pragma unroll
            for (int j = 0; j < 4; j++) {
                const int t = TIDX[ei][j];
                if (t >= 0) {
                    const ulonglong2 qq = (j == 0) ? q0 : (j == 1) ? q1 : (j == 2) ? q2 : q3;
                    const float p = f2hsum(f2fma(qq.y, k.y, f2mul(qq.x, k.x)));
                    shi[j][t - 9] = p;
                }
            }
        }
        #pragma unroll
        for (int j = 0; j < 4; j++) {
            float zhi = txr8(&shi[j][0], lane);
            ejhi[j] = (l0 + j >= offhi) ? __expf(zhi * SCALE) : 0.f;
            // denominator: lanes u,u^1 hold duplicates -> butterfly {2,4,8}
            float sm = ejlo[j] + ejhi[j];
            sm += __shfl_xor_sync(FULL, sm, 2);
            sm += __shfl_xor_sync(FULL, sm, 4);
            sm += __shfl_xor_sync(FULL, sm, 8);
            inv[j] = __fdividef(1.f, sm + e8r[j]);
        }
    }

    // ---------- Phase 3: weighted V accumulation (packed) ----------
    ulonglong2 a0, a1, a2, a3;
    a0.x = a0.y = a1.x = a1.y = a2.x = a2.y = a3.x = a3.y = 0ull;  // +0.0f pair

    #pragma unroll
    for (int ei = 0; ei < 45; ei++) {
        const int e = EREL[ei];
        const bool ok = (l0 >= e);
        const int addr = ok ? (rbase - e * ROWSTR) : rbase;  // clamped
        const ulonglong2 v = *reinterpret_cast<const ulonglong2*>(V + addr);
        #pragma unroll
        for (int j = 0; j < 4; j++) {
            const int t = TIDX[ei][j];
            if (t >= 0) {
                float w;
                if (t == 8)      w = e8r[j];                                  // replicated
                else if (t < 8)  w = __shfl_sync(FULL, ejlo[j], halfbase + 2 * t);
                else             w = __shfl_sync(FULL, ejhi[j], halfbase + 2 * (t - 9));
                // w == 0 exactly for invalid uses -> clamped v is harmless
                const u64 ww = f2dup(w);
                ulonglong2& a = (j == 0) ? a0 : (j == 1) ? a1 : (j == 2) ? a2 : a3;
                a.x = f2fma(ww, v.x, a.x);
                a.y = f2fma(ww, v.y, a.y);
            }
        }
    }

    // denominator division already folded into inv[]; apply packed scale
    const u64 i0 = f2dup(inv[0]);
    const u64 i1 = f2dup(inv[1]);
    const u64 i2 = f2dup(inv[2]);
    const u64 i3 = f2dup(inv[3]);
    a0.x = f2mul(a0.x, i0); a0.y = f2mul(a0.y, i0);
    a1.x = f2mul(a1.x, i1); a1.y = f2mul(a1.y, i1);
    a2.x = f2mul(a2.x, i2); a2.y = f2mul(a2.y, i2);
    a3.x = f2mul(a3.x, i3); a3.y = f2mul(a3.y, i3);

    *reinterpret_cast<ulonglong2*>(O + rbase)              = a0;
    *reinterpret_cast<ulonglong2*>(O + rbase + ROWSTR)     = a1;
    *reinterpret_cast<ulonglong2*>(O + rbase + 2 * ROWSTR) = a2;
    *reinterpret_cast<ulonglong2*>(O + rbase + 3 * ROWSTR) = a3;
}

extern "C" void kernel_launch(void* const* d_in, const int* in_sizes, int n_in,
                              void* d_out, int out_size)
{
    const float* Q = (const float*)d_in[0];
    const float* K = (const float*)d_in[1];
    const float* V = (const float*)d_in[2];
    float* O = (float*)d_out;

    const int nblocks = Bc * Hc * (Lc / 32); // 2048
    sparse_attn_f32x2<<<nblocks, 128>>>(Q, K, V, O);
}